// round 3
// baseline (speedup 1.0000x reference)
#include <cuda_runtime.h>
#include <math.h>

// ---------------------------------------------------------------------------
// SplatPushModel2 — 2-kernel pipeline:
//   k_reduce_all : one block per batch; computes geometry, then the full
//                  dependent scalar chain m_swept -> existing -> dep_sum
//                  with in-block syncs (no atomics, deterministic).
//   k_final      : out = occ*(1-swept) + blur(dep_mask)*dep_norm, copy fast path.
// Sigmoid cutoff CUT=16 -> dropped terms < 1.2e-7 (tol 1e-3).
// ---------------------------------------------------------------------------

#define NB   16
#define HW   1024
#define IMG  (HW*HW)

__device__ __constant__ float KW[9] = {
    0.00761439f, 0.03607498f, 0.10958593f, 0.21344431f, 0.26655960f,
    0.21344431f, 0.10958593f, 0.03607498f, 0.00761439f
};

struct Geo { float p0x, p0y, p1x, p1y, ux, uy, L, pad; };
__device__ Geo  g_geo[NB];
__device__ float g_msw[NB], g_ext[NB], g_dsum[NB];

__device__ __forceinline__ float clampf(float v, float lo, float hi) {
    return fminf(fmaxf(v, lo), hi);
}

// deterministic block-wide sum over 1024 threads; result valid on thread 0,
// broadcast via smem. Must be called by all threads.
__device__ __forceinline__ float blockSum1024(float v) {
    __shared__ float sred[32];
    __shared__ float sbc;
    #pragma unroll
    for (int o = 16; o > 0; o >>= 1) v += __shfl_down_sync(0xffffffffu, v, o);
    int lane = threadIdx.x & 31, wp = threadIdx.x >> 5;
    if (lane == 0) sred[wp] = v;
    __syncthreads();
    if (wp == 0) {
        v = sred[lane];
        #pragma unroll
        for (int o = 16; o > 0; o >>= 1) v += __shfl_down_sync(0xffffffffu, v, o);
        if (lane == 0) sbc = v;
    }
    __syncthreads();
    float r = sbc;
    __syncthreads();
    return r;
}

// One block per batch. 1024 threads. Three dependent reduction phases.
__global__ __launch_bounds__(1024) void k_reduce_all(const float* __restrict__ occ,
                                                     const float* __restrict__ as_,
                                                     const float* __restrict__ ae_) {
    const float WIDTH = 3.0f, CUT = 16.0f, EPS = 1e-8f;
    int b = blockIdx.x;

    __shared__ Geo sg;
    if (threadIdx.x == 0) {
        float p0x = as_[b*3+0], p0y = as_[b*3+1];
        float p1x = ae_[b*3+0], p1y = ae_[b*3+1];
        float dx = p1x - p0x, dy = p1y - p0y;
        float L = sqrtf(dx*dx + dy*dy + EPS);
        float inv = __fdividef(1.0f, L);
        sg.p0x = p0x; sg.p0y = p0y; sg.p1x = p1x; sg.p1y = p1y;
        sg.ux = dx*inv; sg.uy = dy*inv; sg.L = L; sg.pad = 0.f;
        g_geo[b] = sg;
    }
    __syncthreads();
    Geo g = sg;
    const float* rowbase = occ + b*IMG;

    float pile = 0.f, extra = 0.f;

    #pragma unroll
    for (int MODE = 0; MODE < 3; MODE++) {
        // ---- analytic AABB of active band (+ margin) ----
        const float M = CUT + 1.5f;
        float xmin, xmax, ymin, ymax;
        if (MODE == 0) {
            xmin = fminf(g.p0x, g.p1x) - (WIDTH + M);
            xmax = fmaxf(g.p0x, g.p1x) + (WIDTH + M);
            ymin = fminf(g.p0y, g.p1y) - (WIDTH + M);
            ymax = fmaxf(g.p0y, g.p1y) + (WIDTH + M);
        } else {
            float s0  = (MODE == 2) ? extra : 0.f;
            float slo = s0 - M, shi = s0 + pile + M;
            float R   = WIDTH + M;
            float ax = g.ux*slo, bx = g.ux*shi;
            float ay = g.uy*slo, by = g.uy*shi;
            xmin = g.p1x + fminf(ax, bx) - fabsf(g.uy)*R;
            xmax = g.p1x + fmaxf(ax, bx) + fabsf(g.uy)*R;
            ymin = g.p1y + fminf(ay, by) - fabsf(g.ux)*R;
            ymax = g.p1y + fmaxf(ay, by) + fabsf(g.ux)*R;
        }
        int x0 = max(0,    (int)floorf(xmin)) & ~3;      // float4-aligned
        int x1 = min(1023, (int)floorf(xmax) + 1);
        int y0 = max(0,    (int)floorf(ymin));
        int y1 = min(1023, (int)floorf(ymax) + 1);

        float acc = 0.f;
        if (x1 >= x0 && y1 >= y0) {
            int f0  = x0 >> 2;
            int nf  = (x1 >> 2) - f0 + 1;       // float4 columns
            int ny  = y1 - y0 + 1;
            int tot = nf * ny;
            float s0 = (MODE == 2) ? extra : 0.f;

            for (int i = threadIdx.x; i < tot; i += 1024) {
                int fy = i / nf;
                int fx = i - fy * nf;
                int y  = y0 + fy;
                int xs = (f0 + fx) << 2;

                float rho[4] = {1.f, 1.f, 1.f, 1.f};
                if (MODE < 2) {
                    float4 v4 = *(const float4*)(rowbase + y*HW + xs);
                    rho[0]=v4.x; rho[1]=v4.y; rho[2]=v4.z; rho[3]=v4.w;
                }
                float yf = (float)y;
                #pragma unroll
                for (int j = 0; j < 4; j++) {
                    float x = (float)(xs + j);
                    if (MODE == 0) {
                        float rx = x - g.p0x, ry = yf - g.p0y;
                        float t  = clampf(rx*g.ux + ry*g.uy, 0.f, g.L);
                        float ddx = rx - t*g.ux, ddy = ry - t*g.uy;
                        float d2 = ddx*ddx + ddy*ddy + EPS;
                        float R  = WIDTH + CUT;
                        if (d2 < R*R) {
                            float dist = d2 * rsqrtf(d2);
                            acc += rho[j] * __fdividef(1.f, 1.f + __expf(dist - WIDTH));
                        }
                    } else {
                        float qx = x - g.p1x, qy = yf - g.p1y;
                        float s  = qx*g.ux + qy*g.uy;
                        float r  = qy*g.ux - qx*g.uy;
                        float ar = fabsf(r);
                        if (s > s0 - CUT && s < s0 + pile + CUT && ar < WIDTH + CUT) {
                            float den = (1.f + __expf(s0 - s))
                                      * (1.f + __expf(s - s0 - pile))
                                      * (1.f + __expf(ar - WIDTH));
                            acc += rho[j] * __fdividef(1.f, den);
                        }
                    }
                }
            }
        }
        float total = blockSum1024(acc);
        if (MODE == 0) {
            pile = total * (1.0f/6.0f);
            if (threadIdx.x == 0) g_msw[b] = total;
        } else if (MODE == 1) {
            extra = total * (1.0f/6.0f);
            if (threadIdx.x == 0) g_ext[b] = total;
        } else {
            if (threadIdx.x == 0) g_dsum[b] = total;
        }
    }
}

// Final: 128x16 tiles, 512 threads, one float4 per thread. Copy fast-path.
__global__ __launch_bounds__(512) void k_final(const float* __restrict__ occ,
                                               float* __restrict__ out) {
    const float WIDTH = 3.0f, CUT = 16.0f, EPS = 1e-8f;
    int b  = blockIdx.z;
    int w0 = blockIdx.x << 7;   // 0..896 step 128
    int h0 = blockIdx.y << 4;   // 0..1008 step 16
    Geo g = g_geo[b];
    float msw   = g_msw[b];
    float pile  = msw * (1.0f/6.0f);
    float extra = g_ext[b] * (1.0f/6.0f);
    float dnorm = __fdividef(msw, g_dsum[b] + EPS);

    // tile activity (block-uniform)
    float cx = w0 + 63.5f, cy = h0 + 7.5f;
    bool sw_act, dep_act;
    {
        float rx = cx - g.p0x, ry = cy - g.p0y;
        float t  = clampf(rx*g.ux + ry*g.uy, 0.f, g.L);
        float ddx = rx - t*g.ux, ddy = ry - t*g.uy;
        float d2 = ddx*ddx + ddy*ddy;
        float R  = WIDTH + CUT + 65.0f;   // + half-diag of 128x16 tile
        sw_act = d2 < R*R;

        float qx = cx - g.p1x, qy = cy - g.p1y;
        float s  = qx*g.ux + qy*g.uy;
        float r  = qy*g.ux - qx*g.uy;
        float sh = 64.5f*fabsf(g.ux) + 8.5f*fabsf(g.uy);
        float rh = 64.5f*fabsf(g.uy) + 8.5f*fabsf(g.ux);
        float M  = CUT + 6.0f;            // + blur reach
        dep_act = (s + sh > extra - M) && (s - sh < extra + pile + M)
               && (fabsf(r) - rh < WIDTH + M);
    }

    int t  = threadIdx.x;
    int lw = (t & 31) << 2;    // col 0..124
    int lh = t >> 5;           // row 0..15
    int gi = b*IMG + (h0 + lh)*HW + (w0 + lw);
    float4 v = *(const float4*)(occ + gi);

    if (!sw_act && !dep_act) {             // pure copy fast path
        *(float4*)(out + gi) = v;
        return;
    }

    __shared__ float sd [24][136];   // dep_mask with halo 4
    __shared__ float shb[24][128];   // horizontally blurred
    __shared__ float sob[16][128];   // fully blurred * dnorm

    float dep[4] = {0.f, 0.f, 0.f, 0.f};
    if (dep_act) {
        for (int i = t; i < 24*136; i += 512) {
            int r_ = i / 136;
            int c_ = i - r_*136;
            int wx = w0 + c_ - 4, hy = h0 + r_ - 4;
            float val = 0.f;
            if ((unsigned)wx < 1024u && (unsigned)hy < 1024u) {
                float qx = (float)wx - g.p1x, qy = (float)hy - g.p1y;
                float s  = qx*g.ux + qy*g.uy;
                float r  = qy*g.ux - qx*g.uy;
                float ar = fabsf(r);
                if (s > extra - CUT && s < extra + pile + CUT && ar < WIDTH + CUT) {
                    float den = (1.f + __expf(extra - s))
                              * (1.f + __expf(s - extra - pile))
                              * (1.f + __expf(ar - WIDTH));
                    val = __fdividef(1.f, den);
                }
            }
            sd[r_][c_] = val;
        }
        __syncthreads();
        for (int i = t; i < 24*128; i += 512) {
            int r_ = i >> 7, c_ = i & 127;
            float a = 0.f;
            #pragma unroll
            for (int j = 0; j < 9; j++) a = fmaf(KW[j], sd[r_][c_ + j], a);
            shb[r_][c_] = a;
        }
        __syncthreads();
        for (int i = t; i < 16*128; i += 512) {
            int r_ = i >> 7, c_ = i & 127;
            float a = 0.f;
            #pragma unroll
            for (int j = 0; j < 9; j++) a = fmaf(KW[j], shb[r_ + j][c_], a);
            sob[r_][c_] = a * dnorm;
        }
        __syncthreads();
        dep[0] = sob[lh][lw];   dep[1] = sob[lh][lw+1];
        dep[2] = sob[lh][lw+2]; dep[3] = sob[lh][lw+3];
    }

    float in[4] = {v.x, v.y, v.z, v.w};
    float o[4];
    #pragma unroll
    for (int j = 0; j < 4; j++) {
        float x = (float)(w0 + lw + j), y = (float)(h0 + lh);
        float sw = 0.f;
        if (sw_act) {
            float rx = x - g.p0x, ry = y - g.p0y;
            float tt = clampf(rx*g.ux + ry*g.uy, 0.f, g.L);
            float ddx = rx - tt*g.ux, ddy = ry - tt*g.uy;
            float d2 = ddx*ddx + ddy*ddy + EPS;
            float R  = WIDTH + CUT;
            if (d2 < R*R) {
                float dist = d2 * rsqrtf(d2);
                sw = __fdividef(1.f, 1.f + __expf(dist - WIDTH));
            }
        }
        o[j] = in[j]*(1.f - sw) + dep[j];
    }
    *(float4*)(out + gi) = make_float4(o[0], o[1], o[2], o[3]);
}

extern "C" void kernel_launch(void* const* d_in, const int* in_sizes, int n_in,
                              void* d_out, int out_size) {
    const float* occ = (const float*)d_in[0];
    const float* as_ = (const float*)d_in[1];
    const float* ae_ = (const float*)d_in[2];
    float* out = (float*)d_out;

    k_reduce_all<<<NB, 1024>>>(occ, as_, ae_);
    k_final<<<dim3(8, 64, NB), 512>>>(occ, out);
}

// round 4
// speedup vs baseline: 1.0591x; 1.0591x over previous
#include <cuda_runtime.h>
#include <math.h>

// ---------------------------------------------------------------------------
// SplatPushModel2 — 2-kernel pipeline:
//   k_reduce_all : one block/batch; geometry + dependent chain
//                  m_swept -> existing -> dep_sum, scanning ONLY the rotated
//                  band via per-row x-intervals (warp-per-row).
//   k_final      : 128x32 tiles, 2 float4/thread; copy fast path; active
//                  tiles recompute dep_mask in smem (halo 4) + separable blur.
// Sigmoid cutoff CUT=16 -> dropped terms < 1.2e-7 (tol 1e-3).
// ---------------------------------------------------------------------------

#define NB   16
#define HW   1024
#define IMG  (HW*HW)

__device__ __constant__ float KW[9] = {
    0.00761439f, 0.03607498f, 0.10958593f, 0.21344431f, 0.26655960f,
    0.21344431f, 0.10958593f, 0.03607498f, 0.00761439f
};

struct Geo { float p0x, p0y, p1x, p1y, ux, uy, L, pad; };
__device__ Geo  g_geo[NB];
__device__ float g_msw[NB], g_ext[NB], g_dsum[NB];

__device__ __forceinline__ float clampf(float v, float lo, float hi) {
    return fminf(fmaxf(v, lo), hi);
}

// deterministic block-wide sum over 1024 threads; broadcast to all.
__device__ __forceinline__ float blockSum1024(float v) {
    __shared__ float sred[32];
    __shared__ float sbc;
    #pragma unroll
    for (int o = 16; o > 0; o >>= 1) v += __shfl_down_sync(0xffffffffu, v, o);
    int lane = threadIdx.x & 31, wp = threadIdx.x >> 5;
    if (lane == 0) sred[wp] = v;
    __syncthreads();
    if (wp == 0) {
        v = sred[lane];
        #pragma unroll
        for (int o = 16; o > 0; o >>= 1) v += __shfl_down_sync(0xffffffffu, v, o);
        if (lane == 0) sbc = v;
    }
    __syncthreads();
    float r = sbc;
    __syncthreads();
    return r;
}

// x-interval of { slo<=s<=shi, |r|<=R } on scanline y, frame anchored at P.
// s = ux*dx + uy*dy ; r = ux*dy - uy*dx ; dx = x-Px, dy = y-Py.
__device__ __forceinline__ bool rowInterval(float Px, float Py, float ux, float uy,
                                            float slo, float shi, float R, int y,
                                            int& xa, int& xb) {
    float dy = (float)y - Py;
    float A = uy * dy;          // s = ux*dx + A
    float B = ux * dy;          // r = -uy*dx + B
    float dlo = -2048.f, dhi = 2048.f;
    if (fabsf(ux) > 1e-4f) {
        float i0 = (slo - A) / ux, i1 = (shi - A) / ux;
        dlo = fmaxf(dlo, fminf(i0, i1));
        dhi = fminf(dhi, fmaxf(i0, i1));
    } else if (A < slo - 0.25f || A > shi + 0.25f) return false;
    if (fabsf(uy) > 1e-4f) {
        float i0 = (B - R) / uy, i1 = (B + R) / uy;
        dlo = fmaxf(dlo, fminf(i0, i1));
        dhi = fminf(dhi, fmaxf(i0, i1));
    } else if (fabsf(B) > R + 0.25f) return false;
    xa = max(0,    (int)floorf(Px + dlo) - 1);
    xb = min(1023, (int)ceilf (Px + dhi) + 1);
    return xa <= xb;
}

// One block per batch. 1024 threads. Three dependent reduction phases.
__global__ __launch_bounds__(1024) void k_reduce_all(const float* __restrict__ occ,
                                                     const float* __restrict__ as_,
                                                     const float* __restrict__ ae_) {
    const float WIDTH = 3.0f, CUT = 16.0f, EPS = 1e-8f;
    int b = blockIdx.x;

    __shared__ Geo sg;
    if (threadIdx.x == 0) {
        float p0x = as_[b*3+0], p0y = as_[b*3+1];
        float p1x = ae_[b*3+0], p1y = ae_[b*3+1];
        float dx = p1x - p0x, dy = p1y - p0y;
        float L = sqrtf(dx*dx + dy*dy + EPS);
        float inv = __fdividef(1.0f, L);
        sg.p0x = p0x; sg.p0y = p0y; sg.p1x = p1x; sg.p1y = p1y;
        sg.ux = dx*inv; sg.uy = dy*inv; sg.L = L; sg.pad = 0.f;
        g_geo[b] = sg;
    }
    __syncthreads();
    Geo g = sg;
    const float* base = occ + b*IMG;

    int wp = threadIdx.x >> 5, lane = threadIdx.x & 31;
    float pile = 0.f, extra = 0.f;

    #pragma unroll
    for (int MODE = 0; MODE < 3; MODE++) {
        float Px, Py, slo, shi, R, s0;
        if (MODE == 0) {
            Px = g.p0x; Py = g.p0y;
            R  = WIDTH + CUT + 0.5f;
            slo = -R; shi = g.L + R;
            s0 = 0.f;
        } else {
            Px = g.p1x; Py = g.p1y;
            s0  = (MODE == 2) ? extra : 0.f;
            R   = WIDTH + CUT + 0.5f;
            slo = s0 - CUT - 0.5f; shi = s0 + pile + CUT + 0.5f;
        }
        // y-range from rotated-band extents
        float ey = fabsf(g.uy) * fmaxf(fabsf(slo), fabsf(shi)) + fabsf(g.ux) * R;
        float ay = fminf(g.uy*slo, g.uy*shi) - fabsf(g.ux)*R;
        float by = fmaxf(g.uy*slo, g.uy*shi) + fabsf(g.ux)*R;
        (void)ey;
        int y0 = max(0,    (int)floorf(Py + ay) - 1);
        int y1 = min(1023, (int)ceilf (Py + by) + 1);

        float acc = 0.f;
        for (int y = y0 + wp; y <= y1; y += 32) {
            int xa, xb;
            if (!rowInterval(Px, Py, g.ux, g.uy, slo, shi, R, y, xa, xb)) continue;
            float yf = (float)y;
            const float* row = base + y*HW;
            for (int x = xa + lane; x <= xb; x += 32) {
                float xf = (float)x;
                if (MODE == 0) {
                    float rx = xf - g.p0x, ry = yf - g.p0y;
                    float t  = clampf(rx*g.ux + ry*g.uy, 0.f, g.L);
                    float ddx = rx - t*g.ux, ddy = ry - t*g.uy;
                    float d2 = ddx*ddx + ddy*ddy + EPS;
                    float R0 = WIDTH + CUT;
                    if (d2 < R0*R0) {
                        float dist = d2 * rsqrtf(d2);
                        acc += row[x] * __fdividef(1.f, 1.f + __expf(dist - WIDTH));
                    }
                } else {
                    float qx = xf - g.p1x, qy = yf - g.p1y;
                    float s  = qx*g.ux + qy*g.uy;
                    float r  = qy*g.ux - qx*g.uy;
                    float ar = fabsf(r);
                    if (s > s0 - CUT && s < s0 + pile + CUT && ar < WIDTH + CUT) {
                        float den = (1.f + __expf(s0 - s))
                                  * (1.f + __expf(s - s0 - pile))
                                  * (1.f + __expf(ar - WIDTH));
                        float rho = (MODE == 2) ? 1.f : row[x];
                        acc += rho * __fdividef(1.f, den);
                    }
                }
            }
        }
        float total = blockSum1024(acc);
        if (MODE == 0) {
            pile = total * (1.0f/6.0f);
            if (threadIdx.x == 0) g_msw[b] = total;
        } else if (MODE == 1) {
            extra = total * (1.0f/6.0f);
            if (threadIdx.x == 0) g_ext[b] = total;
        } else {
            if (threadIdx.x == 0) g_dsum[b] = total;
        }
    }
}

// Final: 128x32 tiles, 512 threads, 2 float4/thread. Copy fast-path.
__global__ __launch_bounds__(512) void k_final(const float* __restrict__ occ,
                                               float* __restrict__ out) {
    const float WIDTH = 3.0f, CUT = 16.0f, EPS = 1e-8f;
    int b  = blockIdx.z;
    int w0 = blockIdx.x << 7;   // 0..896 step 128
    int h0 = blockIdx.y << 5;   // 0..992 step 32
    Geo g = g_geo[b];
    float msw   = g_msw[b];
    float pile  = msw * (1.0f/6.0f);
    float extra = g_ext[b] * (1.0f/6.0f);
    float dnorm = __fdividef(msw, g_dsum[b] + EPS);

    // tile activity (block-uniform)
    float cx = w0 + 63.5f, cy = h0 + 15.5f;
    bool sw_act, dep_act;
    {
        float rx = cx - g.p0x, ry = cy - g.p0y;
        float t  = clampf(rx*g.ux + ry*g.uy, 0.f, g.L);
        float ddx = rx - t*g.ux, ddy = ry - t*g.uy;
        float d2 = ddx*ddx + ddy*ddy;
        float R  = WIDTH + CUT + 67.0f;   // + half-diag of 128x32 tile
        sw_act = d2 < R*R;

        float qx = cx - g.p1x, qy = cy - g.p1y;
        float s  = qx*g.ux + qy*g.uy;
        float r  = qy*g.ux - qx*g.uy;
        float sh = 64.5f*fabsf(g.ux) + 16.5f*fabsf(g.uy);
        float rh = 64.5f*fabsf(g.uy) + 16.5f*fabsf(g.ux);
        float M  = CUT + 6.0f;            // + blur reach
        dep_act = (s + sh > extra - M) && (s - sh < extra + pile + M)
               && (fabsf(r) - rh < WIDTH + M);
    }

    int t  = threadIdx.x;
    int lw = (t & 31) << 2;    // col 0..124
    int lh = t >> 5;           // row 0..15 (also handles lh+16)
    int gi0 = b*IMG + (h0 + lh)*HW      + (w0 + lw);
    int gi1 = gi0 + 16*HW;
    float4 va = *(const float4*)(occ + gi0);
    float4 vb = *(const float4*)(occ + gi1);

    if (!sw_act && !dep_act) {             // pure copy fast path
        *(float4*)(out + gi0) = va;
        *(float4*)(out + gi1) = vb;
        return;
    }

    __shared__ float sd [40][136];   // dep_mask with halo 4; later aliased by sob
    __shared__ float shb[40][128];   // horizontally blurred
    float (*sob)[128] = (float(*)[128])&sd[0][0];   // 32x128, overlays sd

    float depa[4] = {0.f,0.f,0.f,0.f}, depb[4] = {0.f,0.f,0.f,0.f};
    if (dep_act) {
        for (int i = t; i < 40*136; i += 512) {
            int r_ = i / 136;
            int c_ = i - r_*136;
            int wx = w0 + c_ - 4, hy = h0 + r_ - 4;
            float val = 0.f;
            if ((unsigned)wx < 1024u && (unsigned)hy < 1024u) {
                float qx = (float)wx - g.p1x, qy = (float)hy - g.p1y;
                float s  = qx*g.ux + qy*g.uy;
                float r  = qy*g.ux - qx*g.uy;
                float ar = fabsf(r);
                if (s > extra - CUT && s < extra + pile + CUT && ar < WIDTH + CUT) {
                    float den = (1.f + __expf(extra - s))
                              * (1.f + __expf(s - extra - pile))
                              * (1.f + __expf(ar - WIDTH));
                    val = __fdividef(1.f, den);
                }
            }
            sd[r_][c_] = val;
        }
        __syncthreads();
        for (int i = t; i < 40*128; i += 512) {
            int r_ = i >> 7, c_ = i & 127;
            float a = 0.f;
            #pragma unroll
            for (int j = 0; j < 9; j++) a = fmaf(KW[j], sd[r_][c_ + j], a);
            shb[r_][c_] = a;
        }
        __syncthreads();
        for (int i = t; i < 32*128; i += 512) {
            int r_ = i >> 7, c_ = i & 127;
            float a = 0.f;
            #pragma unroll
            for (int j = 0; j < 9; j++) a = fmaf(KW[j], shb[r_ + j][c_], a);
            sob[r_][c_] = a * dnorm;     // overlays sd (no longer read)
        }
        __syncthreads();
        #pragma unroll
        for (int j = 0; j < 4; j++) {
            depa[j] = sob[lh][lw + j];
            depb[j] = sob[lh + 16][lw + j];
        }
    }

    float ina[4] = {va.x, va.y, va.z, va.w};
    float inb[4] = {vb.x, vb.y, vb.z, vb.w};
    float oa[4], ob[4];
    #pragma unroll
    for (int j = 0; j < 4; j++) {
        float x = (float)(w0 + lw + j);
        #pragma unroll
        for (int rr = 0; rr < 2; rr++) {
            float y = (float)(h0 + lh + rr*16);
            float sw = 0.f;
            if (sw_act) {
                float rx = x - g.p0x, ry = y - g.p0y;
                float tt = clampf(rx*g.ux + ry*g.uy, 0.f, g.L);
                float ddx = rx - tt*g.ux, ddy = ry - tt*g.uy;
                float d2 = ddx*ddx + ddy*ddy + EPS;
                float R  = WIDTH + CUT;
                if (d2 < R*R) {
                    float dist = d2 * rsqrtf(d2);
                    sw = __fdividef(1.f, 1.f + __expf(dist - WIDTH));
                }
            }
            if (rr == 0) oa[j] = ina[j]*(1.f - sw) + depa[j];
            else         ob[j] = inb[j]*(1.f - sw) + depb[j];
        }
    }
    *(float4*)(out + gi0) = make_float4(oa[0], oa[1], oa[2], oa[3]);
    *(float4*)(out + gi1) = make_float4(ob[0], ob[1], ob[2], ob[3]);
}

extern "C" void kernel_launch(void* const* d_in, const int* in_sizes, int n_in,
                              void* d_out, int out_size) {
    const float* occ = (const float*)d_in[0];
    const float* as_ = (const float*)d_in[1];
    const float* ae_ = (const float*)d_in[2];
    float* out = (float*)d_out;

    k_reduce_all<<<NB, 1024>>>(occ, as_, ae_);
    k_final<<<dim3(8, 32, NB), 512>>>(occ, out);
}

// round 5
// speedup vs baseline: 1.2480x; 1.1784x over previous
#include <cuda_runtime.h>
#include <math.h>

// ---------------------------------------------------------------------------
// SplatPushModel2 — forked pipeline:
//   main stream : k_swept  (out = occ*(1-swept), copy fast path; geometry
//                 recomputed inline -> independent of reductions)
//   side stream : k_scalars -> k_red<0> -> k_red<1> -> k_red<2>
//                 (row-interval band scan, many blocks, float atomics)
//   join        : k_depadd (out += blur(dep_mask)*dep_norm over deposit tiles)
// Sigmoid cutoff CUT=16 -> dropped terms < 1.2e-7 (tol 1e-3).
// ---------------------------------------------------------------------------

#define NB   16
#define HW   1024
#define IMG  (HW*HW)

__device__ __constant__ float KW[9] = {
    0.00761439f, 0.03607498f, 0.10958593f, 0.21344431f, 0.26655960f,
    0.21344431f, 0.10958593f, 0.03607498f, 0.00761439f
};

struct Geo { float p0x, p0y, p1x, p1y, ux, uy, L, pad; };
__device__ Geo  g_geo[NB];
__device__ float g_msw[NB], g_ext[NB], g_dsum[NB];

__device__ __forceinline__ float clampf(float v, float lo, float hi) {
    return fminf(fmaxf(v, lo), hi);
}

__global__ void k_scalars(const float* __restrict__ as_, const float* __restrict__ ae_) {
    int b = threadIdx.x;
    if (b < NB) {
        float p0x = as_[b*3+0], p0y = as_[b*3+1];
        float p1x = ae_[b*3+0], p1y = ae_[b*3+1];
        float dx = p1x - p0x, dy = p1y - p0y;
        float L = sqrtf(dx*dx + dy*dy + 1e-8f);
        float inv = __fdividef(1.0f, L);
        Geo g;
        g.p0x = p0x; g.p0y = p0y; g.p1x = p1x; g.p1y = p1y;
        g.ux = dx*inv; g.uy = dy*inv; g.L = L; g.pad = 0.f;
        g_geo[b] = g;
        g_msw[b] = 0.f; g_ext[b] = 0.f; g_dsum[b] = 0.f;
    }
}

// x-interval of { slo<=s<=shi, |r|<=R } on scanline y, frame anchored at P.
__device__ __forceinline__ bool rowInterval(float Px, float Py, float ux, float uy,
                                            float slo, float shi, float R, int y,
                                            int& xa, int& xb) {
    float dy = (float)y - Py;
    float A = uy * dy;          // s = ux*dx + A
    float B = ux * dy;          // r = -uy*dx + B
    float dlo = -2048.f, dhi = 2048.f;
    if (fabsf(ux) > 1e-4f) {
        float i0 = (slo - A) / ux, i1 = (shi - A) / ux;
        dlo = fmaxf(dlo, fminf(i0, i1));
        dhi = fminf(dhi, fmaxf(i0, i1));
    } else if (A < slo - 0.25f || A > shi + 0.25f) return false;
    if (fabsf(uy) > 1e-4f) {
        float i0 = (B - R) / uy, i1 = (B + R) / uy;
        dlo = fmaxf(dlo, fminf(i0, i1));
        dhi = fminf(dhi, fmaxf(i0, i1));
    } else if (fabsf(B) > R + 0.25f) return false;
    xa = max(0,    (int)floorf(Px + dlo) - 1);
    xb = min(1023, (int)ceilf (Px + dhi) + 1);
    return xa <= xb;
}

// MODE 0: m_swept; MODE 1: existing; MODE 2: dep_sum. grid (128, NB), block 64.
template<int MODE>
__global__ __launch_bounds__(64) void k_red(const float* __restrict__ occ) {
    const float WIDTH = 3.0f, CUT = 16.0f, EPS = 1e-8f;
    int b = blockIdx.y;
    Geo g = g_geo[b];
    float pile  = (MODE >= 1) ? g_msw[b] * (1.0f/6.0f) : 0.f;
    float extra = (MODE == 2) ? g_ext[b] * (1.0f/6.0f) : 0.f;

    float Px, Py, slo, shi, R, s0;
    if (MODE == 0) {
        Px = g.p0x; Py = g.p0y;
        R  = WIDTH + CUT + 0.5f;
        slo = -R; shi = g.L + R; s0 = 0.f;
    } else {
        Px = g.p1x; Py = g.p1y;
        s0  = (MODE == 2) ? extra : 0.f;
        R   = WIDTH + CUT + 0.5f;
        slo = s0 - CUT - 0.5f; shi = s0 + pile + CUT + 0.5f;
    }
    float ay = fminf(g.uy*slo, g.uy*shi) - fabsf(g.ux)*R;
    float by = fmaxf(g.uy*slo, g.uy*shi) + fabsf(g.ux)*R;
    int y0 = max(0,    (int)floorf(Py + ay) - 1);
    int y1 = min(1023, (int)ceilf (Py + by) + 1);

    const float* base = occ + b*IMG;
    float acc = 0.f;
    for (int y = y0 + blockIdx.x; y <= y1; y += 128) {
        int xa, xb;
        if (!rowInterval(Px, Py, g.ux, g.uy, slo, shi, R, y, xa, xb)) continue;
        float yf = (float)y;
        const float* row = base + y*HW;
        for (int x = xa + (int)threadIdx.x; x <= xb; x += 64) {
            float xf = (float)x;
            if (MODE == 0) {
                float rx = xf - g.p0x, ry = yf - g.p0y;
                float t  = clampf(rx*g.ux + ry*g.uy, 0.f, g.L);
                float ddx = rx - t*g.ux, ddy = ry - t*g.uy;
                float d2 = ddx*ddx + ddy*ddy + EPS;
                float R0 = WIDTH + CUT;
                if (d2 < R0*R0) {
                    float dist = d2 * rsqrtf(d2);
                    acc += row[x] * __fdividef(1.f, 1.f + __expf(dist - WIDTH));
                }
            } else {
                float qx = xf - g.p1x, qy = yf - g.p1y;
                float s  = qx*g.ux + qy*g.uy;
                float r  = qy*g.ux - qx*g.uy;
                float ar = fabsf(r);
                if (s > s0 - CUT && s < s0 + pile + CUT && ar < WIDTH + CUT) {
                    float den = (1.f + __expf(s0 - s))
                              * (1.f + __expf(s - s0 - pile))
                              * (1.f + __expf(ar - WIDTH));
                    float rho = (MODE == 2) ? 1.f : row[x];
                    acc += rho * __fdividef(1.f, den);
                }
            }
        }
    }
    // 64-thread reduce + one atomic
    __shared__ float s2[2];
    #pragma unroll
    for (int o = 16; o > 0; o >>= 1) acc += __shfl_down_sync(0xffffffffu, acc, o);
    int lane = threadIdx.x & 31, wp = threadIdx.x >> 5;
    if (lane == 0) s2[wp] = acc;
    __syncthreads();
    if (threadIdx.x == 0) {
        float tot = s2[0] + s2[1];
        if (tot != 0.f)
            atomicAdd((MODE == 0) ? &g_msw[b] : ((MODE == 1) ? &g_ext[b] : &g_dsum[b]), tot);
    }
}

// out = occ*(1-swept); 128x64 tiles, 512 threads, 4 float4/thread.
// Geometry computed inline from raw inputs (no dependence on reduce chain).
__global__ __launch_bounds__(512) void k_swept(const float* __restrict__ occ,
                                               const float* __restrict__ as_,
                                               const float* __restrict__ ae_,
                                               float* __restrict__ out) {
    const float WIDTH = 3.0f, CUT = 16.0f, EPS = 1e-8f;
    int b  = blockIdx.z;
    int w0 = blockIdx.x << 7;   // 0..896 step 128
    int h0 = blockIdx.y << 6;   // 0..960 step 64

    float p0x = as_[b*3+0], p0y = as_[b*3+1];
    float p1x = ae_[b*3+0], p1y = ae_[b*3+1];
    float dxl = p1x - p0x, dyl = p1y - p0y;
    float L = sqrtf(dxl*dxl + dyl*dyl + EPS);
    float inv = __fdividef(1.0f, L);
    float ux = dxl*inv, uy = dyl*inv;

    // capsule-distance tile cull
    float cx = w0 + 63.5f, cy = h0 + 31.5f;
    float rxc = cx - p0x, ryc = cy - p0y;
    float tc  = clampf(rxc*ux + ryc*uy, 0.f, L);
    float dcx = rxc - tc*ux, dcy = ryc - tc*uy;
    float Rt  = WIDTH + CUT + 72.0f;   // + half-diag of 128x64 tile
    bool sw_act = (dcx*dcx + dcy*dcy) < Rt*Rt;

    int t  = threadIdx.x;
    int lw = (t & 31) << 2;    // col 0..124
    int lh = t >> 5;           // row 0..15; rows lh+{0,16,32,48}
    int gi = b*IMG + (h0 + lh)*HW + (w0 + lw);

    float4 v0 = *(const float4*)(occ + gi);
    float4 v1 = *(const float4*)(occ + gi + 16*HW);
    float4 v2 = *(const float4*)(occ + gi + 32*HW);
    float4 v3 = *(const float4*)(occ + gi + 48*HW);

    if (!sw_act) {
        *(float4*)(out + gi)         = v0;
        *(float4*)(out + gi + 16*HW) = v1;
        *(float4*)(out + gi + 32*HW) = v2;
        *(float4*)(out + gi + 48*HW) = v3;
        return;
    }

    float in[4][4] = {{v0.x,v0.y,v0.z,v0.w},{v1.x,v1.y,v1.z,v1.w},
                      {v2.x,v2.y,v2.z,v2.w},{v3.x,v3.y,v3.z,v3.w}};
    float o[4][4];
    #pragma unroll
    for (int rr = 0; rr < 4; rr++) {
        float y = (float)(h0 + lh + rr*16);
        float ry = y - p0y;
        #pragma unroll
        for (int j = 0; j < 4; j++) {
            float x  = (float)(w0 + lw + j);
            float rx = x - p0x;
            float tt = clampf(rx*ux + ry*uy, 0.f, L);
            float ddx = rx - tt*ux, ddy = ry - tt*uy;
            float d2 = ddx*ddx + ddy*ddy + EPS;
            float R0 = WIDTH + CUT;
            float sw = 0.f;
            if (d2 < R0*R0) {
                float dist = d2 * rsqrtf(d2);
                sw = __fdividef(1.f, 1.f + __expf(dist - WIDTH));
            }
            o[rr][j] = in[rr][j] * (1.f - sw);
        }
    }
    *(float4*)(out + gi)         = make_float4(o[0][0],o[0][1],o[0][2],o[0][3]);
    *(float4*)(out + gi + 16*HW) = make_float4(o[1][0],o[1][1],o[1][2],o[1][3]);
    *(float4*)(out + gi + 32*HW) = make_float4(o[2][0],o[2][1],o[2][2],o[2][3]);
    *(float4*)(out + gi + 48*HW) = make_float4(o[3][0],o[3][1],o[3][2],o[3][3]);
}

// out += blur(dep_mask)*dep_norm over deposit tiles (32x32, on-device AABB).
__global__ __launch_bounds__(256) void k_depadd(float* __restrict__ out) {
    const float WIDTH = 3.0f, CUT = 16.0f, EPS = 1e-8f;
    int b = blockIdx.y;
    Geo g = g_geo[b];
    float msw   = g_msw[b];
    float pile  = msw * (1.0f/6.0f);
    float extra = g_ext[b] * (1.0f/6.0f);
    float dnorm = __fdividef(msw, g_dsum[b] + EPS);

    // AABB of deposit band + blur margin
    const float M = CUT + 6.5f;
    float slo = extra - M, shi = extra + pile + M;
    float R   = WIDTH + M;
    float ax = g.ux*slo, bx = g.ux*shi;
    float ay = g.uy*slo, by = g.uy*shi;
    float xmin = g.p1x + fminf(ax, bx) - fabsf(g.uy)*R;
    float xmax = g.p1x + fmaxf(ax, bx) + fabsf(g.uy)*R;
    float ymin = g.p1y + fminf(ay, by) - fabsf(g.ux)*R;
    float ymax = g.p1y + fmaxf(ay, by) + fabsf(g.ux)*R;
    int tx0 = max(0, ((int)floorf(xmin)) >> 5);
    int ty0 = max(0, ((int)floorf(ymin)) >> 5);
    int tx1 = min(31, ((int)floorf(xmax)) >> 5);
    int ty1 = min(31, ((int)floorf(ymax)) >> 5);
    int nx = tx1 - tx0 + 1, ny = ty1 - ty0 + 1;
    if (nx <= 0 || ny <= 0) return;
    int nt = nx * ny;

    __shared__ float sd[40][41];   // dep mask + halo 4
    __shared__ float sh[40][32];   // horizontally blurred

    int t = threadIdx.x;
    for (int idx = blockIdx.x; idx < nt; idx += gridDim.x) {
        int tw = (tx0 + idx % nx) << 5;
        int th = (ty0 + idx / nx) << 5;

        // rotated-band tile cull (block-uniform)
        float cx = tw + 15.5f, cy = th + 15.5f;
        float qx = cx - g.p1x, qy = cy - g.p1y;
        float s  = qx*g.ux + qy*g.uy;
        float r  = qy*g.ux - qx*g.uy;
        float he = 16.5f*(fabsf(g.ux) + fabsf(g.uy)) + 6.0f;  // halo+blur reach
        bool active = (s + he > extra - CUT) && (s - he < extra + pile + CUT)
                   && (fabsf(r) - he < WIDTH + CUT);
        if (!active) continue;

        for (int i = t; i < 40*40; i += 256) {
            int r_ = i / 40, c_ = i - r_*40;
            int wx = tw + c_ - 4, hy = th + r_ - 4;
            float val = 0.f;
            if ((unsigned)wx < 1024u && (unsigned)hy < 1024u) {
                float px = (float)wx - g.p1x, py = (float)hy - g.p1y;
                float ss = px*g.ux + py*g.uy;
                float rr = py*g.ux - px*g.uy;
                float ar = fabsf(rr);
                if (ss > extra - CUT && ss < extra + pile + CUT && ar < WIDTH + CUT) {
                    float den = (1.f + __expf(extra - ss))
                              * (1.f + __expf(ss - extra - pile))
                              * (1.f + __expf(ar - WIDTH));
                    val = __fdividef(1.f, den);
                }
            }
            sd[r_][c_] = val;
        }
        __syncthreads();
        for (int i = t; i < 40*32; i += 256) {
            int r_ = i >> 5, c_ = i & 31;
            float a = 0.f;
            #pragma unroll
            for (int j = 0; j < 9; j++) a = fmaf(KW[j], sd[r_][c_ + j], a);
            sh[r_][c_] = a;
        }
        __syncthreads();
        for (int i = t; i < 32*32; i += 256) {
            int r_ = i >> 5, c_ = i & 31;
            float a = 0.f;
            #pragma unroll
            for (int j = 0; j < 9; j++) a = fmaf(KW[j], sh[r_ + j][c_], a);
            int gi = b*IMG + (th + r_)*HW + (tw + c_);
            out[gi] += a * dnorm;
        }
        __syncthreads();
    }
}

extern "C" void kernel_launch(void* const* d_in, const int* in_sizes, int n_in,
                              void* d_out, int out_size) {
    const float* occ = (const float*)d_in[0];
    const float* as_ = (const float*)d_in[1];
    const float* ae_ = (const float*)d_in[2];
    float* out = (float*)d_out;

    // fork a side stream for the scalar-reduction chain (created fresh each
    // call; never destroyed — kernel_launch runs only a handful of times and
    // stream objects are host-side, not device allocations)
    cudaStream_t side;
    cudaEvent_t e_fork, e_join;
    cudaStreamCreateWithFlags(&side, cudaStreamNonBlocking);
    cudaEventCreateWithFlags(&e_fork, cudaEventDisableTiming);
    cudaEventCreateWithFlags(&e_join, cudaEventDisableTiming);

    cudaEventRecord(e_fork, 0);
    cudaStreamWaitEvent(side, e_fork, 0);

    k_scalars<<<1, 32, 0, side>>>(as_, ae_);
    k_red<0><<<dim3(128, NB), 64, 0, side>>>(occ);
    k_red<1><<<dim3(128, NB), 64, 0, side>>>(occ);
    k_red<2><<<dim3(128, NB), 64, 0, side>>>(occ);
    cudaEventRecord(e_join, side);

    k_swept<<<dim3(8, 16, NB), 512>>>(occ, as_, ae_, out);   // overlaps chain

    cudaStreamWaitEvent(0, e_join, 0);
    k_depadd<<<dim3(64, NB), 256>>>(out);
}